// round 4
// baseline (speedup 1.0000x reference)
#include <cuda_runtime.h>
#include <cuda_bf16.h>
#include <mma.h>
#include <cstdint>

using namespace nvcuda;

// Problem dims
#define BB 4
#define TT 512
#define DD 512
#define HH 1024
#define VV 32000
#define MM (BB*TT)                    // 2048 rows
#define NLOGITS ((long long)MM * VV)  // 65,536,000

#define DECAYF 0.60653065971263342f   // exp(-1/2)

// ---------------- scratch ----------------------------------------------------
__device__ float g_u[MM * HH];        // fc1 output (pre-bias), 8 MB
__device__ int   g_cnt[MM];           // spikes per (b,t) row
__device__ int   g_list[MM * HH];     // spike h-indices per row

// ---------------- K0: zero counters ------------------------------------------
__global__ void zero_cnt_kernel() {
    int i = blockIdx.x * blockDim.x + threadIdx.x;
    if (i < MM) g_cnt[i] = 0;
}

// ---------------- K1: bf16 tensor-core GEMM  u = gather(emb) @ W1^T ----------
// Gathers emb rows and converts fp32->bf16 during smem staging (no prepass).
// Block tile 128x128, k-chunk 32. 8 warps: 2(m) x 4(n), warp tile 64x32.
#define GBM 128
#define GBN 128
#define GKC 32
#define KPAD 40   // 80B row pitch: 16B-aligned, LDSM conflict-free

__global__ __launch_bounds__(256) void fc1_kernel(
    const int* __restrict__ ids, const float* __restrict__ emb,
    const float* __restrict__ W1)
{
    __shared__ __align__(16) __nv_bfloat16 As[GBM][KPAD];
    __shared__ __align__(16) __nv_bfloat16 Bs[GBN][KPAD];
    __shared__ int sids[GBM];

    const int bn  = blockIdx.x * GBN;
    const int bm  = blockIdx.y * GBM;
    const int tid = threadIdx.x;
    const int wid = tid >> 5;
    const int wm  = wid & 1;    // 0..1
    const int wn  = wid >> 1;   // 0..3

    if (tid < GBM) sids[tid] = ids[bm + tid];
    __syncthreads();

    wmma::fragment<wmma::accumulator, 16, 16, 16, float> c[4][2];
#pragma unroll
    for (int i = 0; i < 4; i++)
#pragma unroll
        for (int j = 0; j < 2; j++) wmma::fill_fragment(c[i][j], 0.f);

    for (int k0 = 0; k0 < DD; k0 += GKC) {
        // stage A (gathered emb) and B (W1) tiles: fp32 load -> bf16 smem
        // per tile: 128 rows x 32 k = 1024 float4 loads; 4 per thread each
#pragma unroll
        for (int it = 0; it < 4; it++) {
            int idx = tid + it * 256;         // 0..1023
            int row = idx >> 3;               // 0..127
            int kq  = (idx & 7) * 4;          // 0,4,...,28
            {
                float4 v = *(const float4*)(emb + (size_t)sids[row] * DD + k0 + kq);
                __nv_bfloat162* d = (__nv_bfloat162*)&As[row][kq];
                d[0] = __float22bfloat162_rn(make_float2(v.x, v.y));
                d[1] = __float22bfloat162_rn(make_float2(v.z, v.w));
            }
            {
                float4 v = *(const float4*)(W1 + (size_t)(bn + row) * DD + k0 + kq);
                __nv_bfloat162* d = (__nv_bfloat162*)&Bs[row][kq];
                d[0] = __float22bfloat162_rn(make_float2(v.x, v.y));
                d[1] = __float22bfloat162_rn(make_float2(v.z, v.w));
            }
        }
        __syncthreads();

#pragma unroll
        for (int kk = 0; kk < GKC; kk += 16) {
            wmma::fragment<wmma::matrix_a, 16, 16, 16, __nv_bfloat16, wmma::row_major> a[4];
            wmma::fragment<wmma::matrix_b, 16, 16, 16, __nv_bfloat16, wmma::col_major> b[2];
#pragma unroll
            for (int i = 0; i < 4; i++)
                wmma::load_matrix_sync(a[i], &As[wm * 64 + i * 16][kk], KPAD);
#pragma unroll
            for (int j = 0; j < 2; j++)
                wmma::load_matrix_sync(b[j], &Bs[wn * 32 + j * 16][kk], KPAD);
#pragma unroll
            for (int i = 0; i < 4; i++)
#pragma unroll
                for (int j = 0; j < 2; j++)
                    wmma::mma_sync(c[i][j], a[i], b[j], c[i][j]);
        }
        __syncthreads();
    }

    // epilogue: raw GEMM out (bias folded into scan)
#pragma unroll
    for (int i = 0; i < 4; i++)
#pragma unroll
        for (int j = 0; j < 2; j++) {
            float* dst = g_u + (size_t)(bm + wm * 64 + i * 16) * HH
                             + bn + wn * 32 + j * 16;
            wmma::store_matrix_sync(dst, c[i][j], HH, wmma::mem_row_major);
        }
}

// ---------------- K2: LIF scan over T ----------------------------------------
// 32 blocks = 4 batches x 8 h-chunks(128); 128 threads; bias added here.
#define TS 32
__global__ __launch_bounds__(128) void scan_kernel(
    const float* __restrict__ threshold, const float* __restrict__ b1)
{
    __shared__ float su[TS][128];
    const int b   = blockIdx.x >> 3;
    const int hc  = blockIdx.x & 7;
    const int tid = threadIdx.x;
    const int h   = hc * 128 + tid;

    const float thr = threshold[h];
    const float bia = b1[h];
    float m = 0.f;

    for (int t0 = 0; t0 < TT; t0 += TS) {
#pragma unroll
        for (int j = 0; j < 8; j++) {
            int f4  = tid + j * 128;          // 0..1023
            int tt  = f4 >> 5;                // 32 float4 per row
            int hh4 = (f4 & 31) << 2;
            const float* src = g_u + (size_t)(b * TT + t0 + tt) * HH + hc * 128 + hh4;
            *(float4*)&su[tt][hh4] = *(const float4*)src;
        }
        __syncthreads();
#pragma unroll
        for (int tt = 0; tt < TS; tt++) {
            m = fmaf(m, DECAYF, su[tt][tid] + bia);
            if (m >= thr) {
                int row = b * TT + t0 + tt;
                int pos = atomicAdd(&g_cnt[row], 1);
                g_list[(size_t)row * HH + pos] = h;
                m = 0.f;
            }
        }
        __syncthreads();
    }
}

// ---------------- K3a: logits broadcast (NO dependencies) --------------------
// out[row][v] = b2[v] for all rows; pure streaming store. Runs on side stream.
#define RPT 8
__global__ __launch_bounds__(256) void fc2_broadcast_kernel(
    const float* __restrict__ b2, float* __restrict__ out, long long out_size)
{
    int q  = blockIdx.x * 256 + threadIdx.x;   // quad index into V
    int r0 = blockIdx.y * RPT;
    if (q < VV / 4) {
        float4 val = *(const float4*)(b2 + q * 4);
        float* p = out + (size_t)r0 * VV + q * 4;
#pragma unroll
        for (int i = 0; i < RPT; i++) {
            __stcs((float4*)p, val);
            p += VV;
        }
    }
    // tail scalars (avg_spikes, mem_out) -> 0
    if (blockIdx.y == 0 && q == 0) {
        for (long long t = NLOGITS; t < out_size; t++) out[t] = 0.f;
    }
}

// ---------------- K3b: sparse spike corrections (post-scan) ------------------
__global__ __launch_bounds__(256) void fc2_corr_kernel(
    const float* __restrict__ W2, float* __restrict__ out)
{
    int row = blockIdx.x;
    int k = g_cnt[row];
    if (k == 0) return;
    for (int v = threadIdx.x * 4; v < VV; v += 256 * 4) {
        float4 acc = make_float4(0.f, 0.f, 0.f, 0.f);
        for (int s = 0; s < k; s++) {
            int h = g_list[(size_t)row * HH + s];
            const float* w = W2 + (size_t)v * HH + h;
            acc.x += w[0];
            acc.y += w[HH];
            acc.z += w[2 * HH];
            acc.w += w[3 * HH];
        }
        float* p = out + (size_t)row * VV + v;
        float4 o = *(float4*)p;
        o.x += acc.x; o.y += acc.y; o.z += acc.z; o.w += acc.w;
        *(float4*)p = o;
    }
}

// ---------------- launcher: fork-join capture --------------------------------
extern "C" void kernel_launch(void* const* d_in, const int* in_sizes, int n_in,
                              void* d_out, int out_size)
{
    const int*   ids = (const int*)  d_in[0];
    const float* emb = (const float*)d_in[1];
    const float* W1  = (const float*)d_in[2];
    const float* b1  = (const float*)d_in[3];
    const float* W2  = (const float*)d_in[4];
    const float* b2  = (const float*)d_in[5];
    const float* thr = (const float*)d_in[6];
    float* out = (float*)d_out;

    // One-time resource creation (happens on the first, non-captured call).
    static cudaStream_t s2 = nullptr;
    static cudaEvent_t evFork = nullptr, evJoin = nullptr;
    if (s2 == nullptr) {
        cudaStreamCreateWithFlags(&s2, cudaStreamNonBlocking);
        cudaEventCreateWithFlags(&evFork, cudaEventDisableTiming);
        cudaEventCreateWithFlags(&evJoin, cudaEventDisableTiming);
    }

    // Fork: broadcast store of b2 runs concurrently with fc1/scan.
    cudaEventRecord(evFork, 0);
    cudaStreamWaitEvent(s2, evFork, 0);
    {
        dim3 gb((VV / 4 + 255) / 256, MM / RPT);   // (32, 256)
        fc2_broadcast_kernel<<<gb, 256, 0, s2>>>(b2, out, (long long)out_size);
    }
    cudaEventRecord(evJoin, s2);

    // Main path
    zero_cnt_kernel<<<(MM + 255) / 256, 256>>>();

    dim3 g1(HH / GBN, MM / GBM);                   // (8, 16)
    fc1_kernel<<<g1, 256>>>(ids, emb, W1);

    scan_kernel<<<32, 128>>>(thr, b1);

    // Join: corrections applied after broadcast + scan both done.
    cudaStreamWaitEvent(0, evJoin, 0);
    fc2_corr_kernel<<<MM, 256>>>(W2, out);
}

// round 5
// speedup vs baseline: 1.1512x; 1.1512x over previous
#include <cuda_runtime.h>
#include <cuda_bf16.h>
#include <mma.h>
#include <cstdint>

using namespace nvcuda;

// Problem dims
#define BB 4
#define TT 512
#define DD 512
#define HH 1024
#define VV 32000
#define MM (BB*TT)                    // 2048 rows
#define NLOGITS ((long long)MM * VV)  // 65,536,000

#define DECAYF 0.60653065971263342f   // exp(-1/2)
#define DEC32F 1.1253517471925912e-07f // decay^32 = exp(-16)
#define NCK 16                         // time chunks
#define CKL 32                         // chunk length (NCK*CKL = TT)

// ---------------- scratch ----------------------------------------------------
__device__ float g_u[MM * HH];           // fc1 output (pre-bias), 8 MB
__device__ int   g_cnt[MM];              // spikes per (b,t) row
__device__ int   g_list[MM * HH];        // spike h-indices per row
__device__ float g_carry[BB * NCK * HH]; // chunk carries
__device__ float g_mstart[BB * NCK * HH];// membrane at chunk start
__device__ int   g_flag[BB * HH];        // neuron needs sequential repair

// ---------------- K0: zero counters + flags ----------------------------------
__global__ void zero_kernel() {
    int i = blockIdx.x * blockDim.x + threadIdx.x;
    if (i < MM) g_cnt[i] = 0;
    if (i < BB * HH) g_flag[i] = 0;
}

// ---------------- K1: bf16 tensor-core GEMM  u = gather(emb) @ W1^T ----------
#define GBM 128
#define GBN 128
#define GKC 32
#define KPAD 40   // 80B row pitch: 16B-aligned, LDSM conflict-free

__global__ __launch_bounds__(256) void fc1_kernel(
    const int* __restrict__ ids, const float* __restrict__ emb,
    const float* __restrict__ W1)
{
    __shared__ __align__(16) __nv_bfloat16 As[GBM][KPAD];
    __shared__ __align__(16) __nv_bfloat16 Bs[GBN][KPAD];
    __shared__ int sids[GBM];

    const int bn  = blockIdx.x * GBN;
    const int bm  = blockIdx.y * GBM;
    const int tid = threadIdx.x;
    const int wid = tid >> 5;
    const int wm  = wid & 1;
    const int wn  = wid >> 1;

    if (tid < GBM) sids[tid] = ids[bm + tid];
    __syncthreads();

    wmma::fragment<wmma::accumulator, 16, 16, 16, float> c[4][2];
#pragma unroll
    for (int i = 0; i < 4; i++)
#pragma unroll
        for (int j = 0; j < 2; j++) wmma::fill_fragment(c[i][j], 0.f);

    for (int k0 = 0; k0 < DD; k0 += GKC) {
#pragma unroll
        for (int it = 0; it < 4; it++) {
            int idx = tid + it * 256;         // 0..1023
            int row = idx >> 3;               // 0..127
            int kq  = (idx & 7) * 4;          // 0,4,...,28
            {
                float4 v = *(const float4*)(emb + (size_t)sids[row] * DD + k0 + kq);
                __nv_bfloat162* d = (__nv_bfloat162*)&As[row][kq];
                d[0] = __float22bfloat162_rn(make_float2(v.x, v.y));
                d[1] = __float22bfloat162_rn(make_float2(v.z, v.w));
            }
            {
                float4 v = *(const float4*)(W1 + (size_t)(bn + row) * DD + k0 + kq);
                __nv_bfloat162* d = (__nv_bfloat162*)&Bs[row][kq];
                d[0] = __float22bfloat162_rn(make_float2(v.x, v.y));
                d[1] = __float22bfloat162_rn(make_float2(v.z, v.w));
            }
        }
        __syncthreads();

#pragma unroll
        for (int kk = 0; kk < GKC; kk += 16) {
            wmma::fragment<wmma::matrix_a, 16, 16, 16, __nv_bfloat16, wmma::row_major> a[4];
            wmma::fragment<wmma::matrix_b, 16, 16, 16, __nv_bfloat16, wmma::col_major> b[2];
#pragma unroll
            for (int i = 0; i < 4; i++)
                wmma::load_matrix_sync(a[i], &As[wm * 64 + i * 16][kk], KPAD);
#pragma unroll
            for (int j = 0; j < 2; j++)
                wmma::load_matrix_sync(b[j], &Bs[wn * 32 + j * 16][kk], KPAD);
#pragma unroll
            for (int i = 0; i < 4; i++)
#pragma unroll
                for (int j = 0; j < 2; j++)
                    wmma::mma_sync(c[i][j], a[i], b[j], c[i][j]);
        }
        __syncthreads();
    }

#pragma unroll
    for (int i = 0; i < 4; i++)
#pragma unroll
        for (int j = 0; j < 2; j++) {
            float* dst = g_u + (size_t)(bm + wm * 64 + i * 16) * HH
                             + bn + wn * 32 + j * 16;
            wmma::store_matrix_sync(dst, c[i][j], HH, wmma::mem_row_major);
        }
}

// ---------------- K2a: chunk-local carries (parallel over time) --------------
// carry[b][ck][h] = sum_{i<32} decay^(31-i) * (u[b][ck*32+i][h] + b1[h])
__global__ __launch_bounds__(512) void scan_carry_kernel(const float* __restrict__ b1)
{
    int bc = blockIdx.x;                 // 0..63 = b*NCK+ck
    int b  = bc >> 4, ck = bc & 15;
    int h  = blockIdx.y * 512 + threadIdx.x;
    float bia = b1[h];
    const float* up = g_u + (size_t)(b * TT + ck * CKL) * HH + h;
    float c = 0.f;
#pragma unroll
    for (int i = 0; i < CKL; i++)
        c = fmaf(c, DECAYF, up[(size_t)i * HH] + bia);
    g_carry[(size_t)bc * HH + h] = c;
}

// ---------------- K2b: chain chunk carries (tiny sequential) -----------------
__global__ __launch_bounds__(512) void scan_mstart_kernel()
{
    int b = blockIdx.x;                  // 0..3
    int h = blockIdx.y * 512 + threadIdx.x;
    float m = 0.f;
#pragma unroll
    for (int ck = 0; ck < NCK; ck++) {
        size_t idx = (size_t)(b * NCK + ck) * HH + h;
        g_mstart[idx] = m;
        m = fmaf(m, DEC32F, g_carry[idx]);
    }
}

// ---------------- K2c: crossing detection (parallel over time) ---------------
// Linear (no-reset) membrane == true membrane while no spike has occurred;
// if the linear trajectory never reaches thr, the neuron provably never spikes.
__global__ __launch_bounds__(512) void scan_check_kernel(
    const float* __restrict__ thr_, const float* __restrict__ b1)
{
    int bc = blockIdx.x;
    int b  = bc >> 4, ck = bc & 15;
    int h  = blockIdx.y * 512 + threadIdx.x;
    float thr = thr_[h];
    float bia = b1[h];
    float m = g_mstart[(size_t)bc * HH + h];
    const float* up = g_u + (size_t)(b * TT + ck * CKL) * HH + h;
    int fire = 0;
#pragma unroll
    for (int i = 0; i < CKL; i++) {
        m = fmaf(m, DECAYF, up[(size_t)i * HH] + bia);
        fire |= (m >= thr);
    }
    if (fire) g_flag[b * HH + h] = 1;
}

// ---------------- K2d: exact sequential repair for flagged neurons -----------
__global__ __launch_bounds__(512) void repair_kernel(
    const float* __restrict__ thr_, const float* __restrict__ b1)
{
    int b = blockIdx.x;
    int h = blockIdx.y * 512 + threadIdx.x;
    if (!g_flag[b * HH + h]) return;
    float thr = thr_[h];
    float bia = b1[h];
    float m = 0.f;
    for (int t = 0; t < TT; t++) {
        m = fmaf(m, DECAYF, g_u[(size_t)(b * TT + t) * HH + h] + bia);
        if (m >= thr) {
            int row = b * TT + t;
            int pos = atomicAdd(&g_cnt[row], 1);
            g_list[(size_t)row * HH + pos] = h;
            m = 0.f;
        }
    }
}

// ---------------- K3a: logits broadcast (side stream, SM-limited) ------------
// 64 resident blocks: saturates store BW, leaves SMs for the main path.
__global__ __launch_bounds__(256) void fc2_broadcast_kernel(
    const float* __restrict__ b2, float* __restrict__ out, long long out_size)
{
    int q = blockIdx.x * 256 + threadIdx.x;     // v-quad, 0..8191
    if (q < VV / 4) {
        float4 val = *(const float4*)(b2 + q * 4);
        int r0 = blockIdx.y * (MM / 2);
        float* p = out + (size_t)r0 * VV + q * 4;
#pragma unroll 8
        for (int i = 0; i < MM / 2; i++) {
            __stcs((float4*)p, val);
            p += VV;
        }
    }
    // tail scalars (avg_spikes, mem_out) -> 0
    if (blockIdx.y == 0 && q == 0)
        for (long long t = NLOGITS; t < out_size; t++) out[t] = 0.f;
}

// ---------------- K3b: sparse spike corrections (post-scan + join) -----------
__global__ __launch_bounds__(256) void fc2_corr_kernel(
    const float* __restrict__ W2, float* __restrict__ out)
{
    int row = blockIdx.x;
    int k = g_cnt[row];
    if (k == 0) return;
    for (int v = threadIdx.x * 4; v < VV; v += 256 * 4) {
        float4 acc = make_float4(0.f, 0.f, 0.f, 0.f);
        for (int s = 0; s < k; s++) {
            int h = g_list[(size_t)row * HH + s];
            const float* w = W2 + (size_t)v * HH + h;
            acc.x += w[0];
            acc.y += w[HH];
            acc.z += w[2 * HH];
            acc.w += w[3 * HH];
        }
        float* p = out + (size_t)row * VV + v;
        float4 o = *(float4*)p;
        o.x += acc.x; o.y += acc.y; o.z += acc.z; o.w += acc.w;
        *(float4*)p = o;
    }
}

// ---------------- launcher: fork-join capture --------------------------------
extern "C" void kernel_launch(void* const* d_in, const int* in_sizes, int n_in,
                              void* d_out, int out_size)
{
    const int*   ids = (const int*)  d_in[0];
    const float* emb = (const float*)d_in[1];
    const float* W1  = (const float*)d_in[2];
    const float* b1  = (const float*)d_in[3];
    const float* W2  = (const float*)d_in[4];
    const float* b2  = (const float*)d_in[5];
    const float* thr = (const float*)d_in[6];
    float* out = (float*)d_out;

    static cudaStream_t s2 = nullptr;
    static cudaEvent_t evFork = nullptr, evJoin = nullptr;
    if (s2 == nullptr) {
        cudaStreamCreateWithFlags(&s2, cudaStreamNonBlocking);
        cudaEventCreateWithFlags(&evFork, cudaEventDisableTiming);
        cudaEventCreateWithFlags(&evJoin, cudaEventDisableTiming);
    }

    // Fork: b2 broadcast runs concurrently with the whole main path.
    cudaEventRecord(evFork, 0);
    cudaStreamWaitEvent(s2, evFork, 0);
    {
        dim3 gb(32, 2);   // 64 resident blocks
        fc2_broadcast_kernel<<<gb, 256, 0, s2>>>(b2, out, (long long)out_size);
    }
    cudaEventRecord(evJoin, s2);

    // Main path
    zero_kernel<<<(BB * HH + 255) / 256, 256>>>();

    dim3 g1(HH / GBN, MM / GBM);                   // (8, 16)
    fc1_kernel<<<g1, 256>>>(ids, emb, W1);

    dim3 gs(BB * NCK, 2);                          // (64, 2) x 512
    scan_carry_kernel<<<gs, 512>>>(b1);
    scan_mstart_kernel<<<dim3(BB, 2), 512>>>();
    scan_check_kernel<<<gs, 512>>>(thr, b1);
    repair_kernel<<<dim3(BB, 2), 512>>>(thr, b1);

    // Join: corrections after broadcast + scan both complete.
    cudaStreamWaitEvent(0, evJoin, 0);
    fc2_corr_kernel<<<MM, 256>>>(W2, out);
}

// round 6
// speedup vs baseline: 1.1935x; 1.0368x over previous
#include <cuda_runtime.h>
#include <cuda_bf16.h>
#include <mma.h>
#include <cstdint>

using namespace nvcuda;

// Problem dims
#define BB 4
#define TT 512
#define DD 512
#define HH 1024
#define VV 32000
#define MM (BB*TT)                    // 2048 rows
#define NLOGITS ((long long)MM * VV)  // 65,536,000

#define DECAYF 0.60653065971263342f    // exp(-1/2)
#define DEC32F 1.1253517471925912e-07f // decay^32 = exp(-16)
#define NCK 16                         // time chunks
#define CKL 32                         // chunk length (NCK*CKL = TT)

// ---------------- scratch ----------------------------------------------------
__device__ float g_u[MM * HH];           // fc1 output (pre-bias), 8 MB
__device__ int   g_cnt[MM];              // spikes per (b,t) row
__device__ int   g_list[MM * HH];        // spike h-indices per row
__device__ float g_carry[BB * NCK * HH]; // chunk carries
__device__ float g_mstart[BB * NCK * HH];// membrane at chunk start
__device__ int   g_flag[BB * HH];        // neuron needs sequential repair

// ---------------- K1: bf16 tensor-core GEMM  u = gather(emb) @ W1^T ----------
#define GBM 128
#define GBN 128
#define GKC 32
#define KPAD 40   // 80B row pitch: 16B-aligned, LDSM conflict-free

__global__ __launch_bounds__(256) void fc1_kernel(
    const int* __restrict__ ids, const float* __restrict__ emb,
    const float* __restrict__ W1)
{
    __shared__ __align__(16) __nv_bfloat16 As[GBM][KPAD];
    __shared__ __align__(16) __nv_bfloat16 Bs[GBN][KPAD];
    __shared__ int sids[GBM];

    const int bn  = blockIdx.x * GBN;
    const int bm  = blockIdx.y * GBM;
    const int tid = threadIdx.x;
    const int wid = tid >> 5;
    const int wm  = wid & 1;
    const int wn  = wid >> 1;

    if (tid < GBM) sids[tid] = ids[bm + tid];
    __syncthreads();

    wmma::fragment<wmma::accumulator, 16, 16, 16, float> c[4][2];
#pragma unroll
    for (int i = 0; i < 4; i++)
#pragma unroll
        for (int j = 0; j < 2; j++) wmma::fill_fragment(c[i][j], 0.f);

    for (int k0 = 0; k0 < DD; k0 += GKC) {
#pragma unroll
        for (int it = 0; it < 4; it++) {
            int idx = tid + it * 256;         // 0..1023
            int row = idx >> 3;               // 0..127
            int kq  = (idx & 7) * 4;          // 0,4,...,28
            {
                float4 v = *(const float4*)(emb + (size_t)sids[row] * DD + k0 + kq);
                __nv_bfloat162* d = (__nv_bfloat162*)&As[row][kq];
                d[0] = __float22bfloat162_rn(make_float2(v.x, v.y));
                d[1] = __float22bfloat162_rn(make_float2(v.z, v.w));
            }
            {
                float4 v = *(const float4*)(W1 + (size_t)(bn + row) * DD + k0 + kq);
                __nv_bfloat162* d = (__nv_bfloat162*)&Bs[row][kq];
                d[0] = __float22bfloat162_rn(make_float2(v.x, v.y));
                d[1] = __float22bfloat162_rn(make_float2(v.z, v.w));
            }
        }
        __syncthreads();

#pragma unroll
        for (int kk = 0; kk < GKC; kk += 16) {
            wmma::fragment<wmma::matrix_a, 16, 16, 16, __nv_bfloat16, wmma::row_major> a[4];
            wmma::fragment<wmma::matrix_b, 16, 16, 16, __nv_bfloat16, wmma::col_major> b[2];
#pragma unroll
            for (int i = 0; i < 4; i++)
                wmma::load_matrix_sync(a[i], &As[wm * 64 + i * 16][kk], KPAD);
#pragma unroll
            for (int j = 0; j < 2; j++)
                wmma::load_matrix_sync(b[j], &Bs[wn * 32 + j * 16][kk], KPAD);
#pragma unroll
            for (int i = 0; i < 4; i++)
#pragma unroll
                for (int j = 0; j < 2; j++)
                    wmma::mma_sync(c[i][j], a[i], b[j], c[i][j]);
        }
        __syncthreads();
    }

#pragma unroll
    for (int i = 0; i < 4; i++)
#pragma unroll
        for (int j = 0; j < 2; j++) {
            float* dst = g_u + (size_t)(bm + wm * 64 + i * 16) * HH
                             + bn + wn * 32 + j * 16;
            wmma::store_matrix_sync(dst, c[i][j], HH, wmma::mem_row_major);
        }
}

// ---------------- K2a: chunk-local carries (parallel over time) --------------
__global__ __launch_bounds__(512) void scan_carry_kernel(const float* __restrict__ b1)
{
    int bc = blockIdx.x;                 // 0..63 = b*NCK+ck
    int b  = bc >> 4, ck = bc & 15;
    int h  = blockIdx.y * 512 + threadIdx.x;
    float bia = b1[h];
    const float* up = g_u + (size_t)(b * TT + ck * CKL) * HH + h;
    float c = 0.f;
#pragma unroll
    for (int i = 0; i < CKL; i++)
        c = fmaf(c, DECAYF, up[(size_t)i * HH] + bia);
    g_carry[(size_t)bc * HH + h] = c;
}

// ---------------- K2b: chain carries + zero counters/flags -------------------
__global__ __launch_bounds__(512) void scan_mstart_kernel()
{
    int b = blockIdx.x;                  // 0..3
    int h = blockIdx.y * 512 + threadIdx.x;
    // fold bookkeeping zeroing in here (4096 threads total)
    int gt = (b * 2 + blockIdx.y) * 512 + threadIdx.x;   // 0..4095
    if (gt < MM) g_cnt[gt] = 0;
    g_flag[b * HH + h] = 0;

    float m = 0.f;
#pragma unroll
    for (int ck = 0; ck < NCK; ck++) {
        size_t idx = (size_t)(b * NCK + ck) * HH + h;
        g_mstart[idx] = m;
        m = fmaf(m, DEC32F, g_carry[idx]);
    }
}

// ---------------- K2c: crossing detection (parallel over time) ---------------
// Linear (no-reset) membrane == true membrane while no spike has occurred;
// if the linear trajectory never reaches thr, the neuron provably never spikes.
__global__ __launch_bounds__(512) void scan_check_kernel(
    const float* __restrict__ thr_, const float* __restrict__ b1)
{
    int bc = blockIdx.x;
    int b  = bc >> 4, ck = bc & 15;
    int h  = blockIdx.y * 512 + threadIdx.x;
    float thr = thr_[h];
    float bia = b1[h];
    float m = g_mstart[(size_t)bc * HH + h];
    const float* up = g_u + (size_t)(b * TT + ck * CKL) * HH + h;
    int fire = 0;
#pragma unroll
    for (int i = 0; i < CKL; i++) {
        m = fmaf(m, DECAYF, up[(size_t)i * HH] + bia);
        fire |= (m >= thr);
    }
    if (fire) g_flag[b * HH + h] = 1;
}

// ---------------- K2d: exact sequential repair for flagged neurons -----------
__global__ __launch_bounds__(512) void repair_kernel(
    const float* __restrict__ thr_, const float* __restrict__ b1)
{
    int b = blockIdx.x;
    int h = blockIdx.y * 512 + threadIdx.x;
    if (!g_flag[b * HH + h]) return;
    float thr = thr_[h];
    float bia = b1[h];
    float m = 0.f;
    for (int t = 0; t < TT; t++) {
        m = fmaf(m, DECAYF, g_u[(size_t)(b * TT + t) * HH + h] + bia);
        if (m >= thr) {
            int row = b * TT + t;
            int pos = atomicAdd(&g_cnt[row], 1);
            g_list[(size_t)row * HH + pos] = h;
            m = 0.f;
        }
    }
}

// ---------------- K3a: logits broadcast (side stream) ------------------------
// 256 blocks: fully co-resident (overlaps main path) AND store-saturating.
#define BROWS 256   // rows per block (MM / gridDim.y)
__global__ __launch_bounds__(256) void fc2_broadcast_kernel(
    const float* __restrict__ b2, float* __restrict__ out, long long out_size)
{
    int q = blockIdx.x * 256 + threadIdx.x;     // v-quad, 0..8191
    if (q < VV / 4) {
        float4 val = *(const float4*)(b2 + q * 4);
        int r0 = blockIdx.y * BROWS;
        float* p = out + (size_t)r0 * VV + q * 4;
#pragma unroll 8
        for (int i = 0; i < BROWS; i++) {
            __stcs((float4*)p, val);
            p += VV;
        }
    }
    // tail scalars (avg_spikes, mem_out) -> 0
    if (blockIdx.y == 0 && q == 0)
        for (long long t = NLOGITS; t < out_size; t++) out[t] = 0.f;
}

// ---------------- K3b: sparse spike corrections (post-scan + join) -----------
__global__ __launch_bounds__(256) void fc2_corr_kernel(
    const float* __restrict__ W2, float* __restrict__ out)
{
    int row = blockIdx.x;
    int k = g_cnt[row];
    if (k == 0) return;
    for (int v = threadIdx.x * 4; v < VV; v += 256 * 4) {
        float4 acc = make_float4(0.f, 0.f, 0.f, 0.f);
        for (int s = 0; s < k; s++) {
            int h = g_list[(size_t)row * HH + s];
            const float* w = W2 + (size_t)v * HH + h;
            acc.x += w[0];
            acc.y += w[HH];
            acc.z += w[2 * HH];
            acc.w += w[3 * HH];
        }
        float* p = out + (size_t)row * VV + v;
        float4 o = *(float4*)p;
        o.x += acc.x; o.y += acc.y; o.z += acc.z; o.w += acc.w;
        *(float4*)p = o;
    }
}

// ---------------- launcher: fork-join capture --------------------------------
extern "C" void kernel_launch(void* const* d_in, const int* in_sizes, int n_in,
                              void* d_out, int out_size)
{
    const int*   ids = (const int*)  d_in[0];
    const float* emb = (const float*)d_in[1];
    const float* W1  = (const float*)d_in[2];
    const float* b1  = (const float*)d_in[3];
    const float* W2  = (const float*)d_in[4];
    const float* b2  = (const float*)d_in[5];
    const float* thr = (const float*)d_in[6];
    float* out = (float*)d_out;

    static cudaStream_t s2 = nullptr;
    static cudaEvent_t evFork = nullptr, evJoin = nullptr;
    if (s2 == nullptr) {
        cudaStreamCreateWithFlags(&s2, cudaStreamNonBlocking);
        cudaEventCreateWithFlags(&evFork, cudaEventDisableTiming);
        cudaEventCreateWithFlags(&evJoin, cudaEventDisableTiming);
    }

    // Fork: b2 broadcast runs concurrently with the whole main path.
    cudaEventRecord(evFork, 0);
    cudaStreamWaitEvent(s2, evFork, 0);
    {
        dim3 gb(32, MM / BROWS);   // (32, 8) = 256 blocks, fully resident
        fc2_broadcast_kernel<<<gb, 256, 0, s2>>>(b2, out, (long long)out_size);
    }
    cudaEventRecord(evJoin, s2);

    // Main path
    dim3 g1(HH / GBN, MM / GBM);                   // (8, 16)
    fc1_kernel<<<g1, 256>>>(ids, emb, W1);

    dim3 gs(BB * NCK, 2);                          // (64, 2) x 512
    scan_carry_kernel<<<gs, 512>>>(b1);
    scan_mstart_kernel<<<dim3(BB, 2), 512>>>();
    scan_check_kernel<<<gs, 512>>>(thr, b1);
    repair_kernel<<<dim3(BB, 2), 512>>>(thr, b1);

    // Join: corrections after broadcast + scan both complete.
    cudaStreamWaitEvent(0, evJoin, 0);
    fc2_corr_kernel<<<MM, 256>>>(W2, out);
}

// round 7
// speedup vs baseline: 1.2698x; 1.0638x over previous
#include <cuda_runtime.h>
#include <cuda_bf16.h>
#include <mma.h>
#include <cstdint>

using namespace nvcuda;

// Problem dims
#define BB 4
#define TT 512
#define DD 512
#define HH 1024
#define VV 32000
#define MM (BB*TT)                    // 2048 rows
#define NLOGITS ((long long)MM * VV)  // 65,536,000

#define DECAYF 0.60653065971263342f    // exp(-1/2)
#define INVDEC 1.64872127070012819f    // exp(+1/2)
#define DEC32F 1.1253517471925912e-07f // decay^32 = exp(-16)
#define NCK 16                         // time chunks
#define CKL 32                         // chunk length (NCK*CKL = TT)

// ---------------- scratch ----------------------------------------------------
__device__ float g_u[MM * HH];           // fc1 output (pre-bias), 8 MB
__device__ int   g_cnt[MM];              // spikes per (b,t) row
__device__ int   g_list[MM * HH];        // spike h-indices per row
__device__ float g_carry[BB * NCK * HH]; // chunk carries
__device__ float g_amin[BB * NCK * HH];  // min mstart that would fire in chunk
__device__ int   g_flag[BB * HH];        // neuron needs sequential repair

// ---------------- K1: bf16 tensor-core GEMM  u = gather(emb) @ W1^T ----------
#define GBM 128
#define GBN 128
#define GKC 32
#define KPAD 40   // 80B row pitch: 16B-aligned, LDSM conflict-free

__global__ __launch_bounds__(256) void fc1_kernel(
    const int* __restrict__ ids, const float* __restrict__ emb,
    const float* __restrict__ W1)
{
    __shared__ __align__(16) __nv_bfloat16 As[GBM][KPAD];
    __shared__ __align__(16) __nv_bfloat16 Bs[GBN][KPAD];
    __shared__ int sids[GBM];

    const int bn  = blockIdx.x * GBN;
    const int bm  = blockIdx.y * GBM;
    const int tid = threadIdx.x;
    const int wid = tid >> 5;
    const int wm  = wid & 1;
    const int wn  = wid >> 1;

    if (tid < GBM) sids[tid] = ids[bm + tid];
    __syncthreads();

    wmma::fragment<wmma::accumulator, 16, 16, 16, float> c[4][2];
#pragma unroll
    for (int i = 0; i < 4; i++)
#pragma unroll
        for (int j = 0; j < 2; j++) wmma::fill_fragment(c[i][j], 0.f);

    for (int k0 = 0; k0 < DD; k0 += GKC) {
#pragma unroll
        for (int it = 0; it < 4; it++) {
            int idx = tid + it * 256;         // 0..1023
            int row = idx >> 3;               // 0..127
            int kq  = (idx & 7) * 4;          // 0,4,...,28
            {
                float4 v = *(const float4*)(emb + (size_t)sids[row] * DD + k0 + kq);
                __nv_bfloat162* d = (__nv_bfloat162*)&As[row][kq];
                d[0] = __float22bfloat162_rn(make_float2(v.x, v.y));
                d[1] = __float22bfloat162_rn(make_float2(v.z, v.w));
            }
            {
                float4 v = *(const float4*)(W1 + (size_t)(bn + row) * DD + k0 + kq);
                __nv_bfloat162* d = (__nv_bfloat162*)&Bs[row][kq];
                d[0] = __float22bfloat162_rn(make_float2(v.x, v.y));
                d[1] = __float22bfloat162_rn(make_float2(v.z, v.w));
            }
        }
        __syncthreads();

#pragma unroll
        for (int kk = 0; kk < GKC; kk += 16) {
            wmma::fragment<wmma::matrix_a, 16, 16, 16, __nv_bfloat16, wmma::row_major> a[4];
            wmma::fragment<wmma::matrix_b, 16, 16, 16, __nv_bfloat16, wmma::col_major> b[2];
#pragma unroll
            for (int i = 0; i < 4; i++)
                wmma::load_matrix_sync(a[i], &As[wm * 64 + i * 16][kk], KPAD);
#pragma unroll
            for (int j = 0; j < 2; j++)
                wmma::load_matrix_sync(b[j], &Bs[wn * 32 + j * 16][kk], KPAD);
#pragma unroll
            for (int i = 0; i < 4; i++)
#pragma unroll
                for (int j = 0; j < 2; j++)
                    wmma::mma_sync(c[i][j], a[i], b[j], c[i][j]);
        }
        __syncthreads();
    }

#pragma unroll
    for (int i = 0; i < 4; i++)
#pragma unroll
        for (int j = 0; j < 2; j++) {
            float* dst = g_u + (size_t)(bm + wm * 64 + i * 16) * HH
                             + bn + wn * 32 + j * 16;
            wmma::store_matrix_sync(dst, c[i][j], HH, wmma::mem_row_major);
        }
}

// ---------------- K2a: chunk carries + fire-threshold on mstart --------------
// carry = sum decay^(31-i)(u_i+b);  within chunk, membrane after step i is
// m_i = mstart*decay^(i+1) + L_i, so the chunk fires iff
// mstart >= min_i (thr - L_i) * decay^-(i+1)  (stored as g_amin, with -1e-6
// conservative margin; repair is exact so false positives are harmless).
__global__ __launch_bounds__(512) void scan_carry_kernel(
    const float* __restrict__ b1, const float* __restrict__ thr_)
{
    int bc = blockIdx.x;                 // 0..63 = b*NCK+ck
    int b  = bc >> 4, ck = bc & 15;
    int h  = blockIdx.y * 512 + threadIdx.x;
    float bia = b1[h];
    float thr = thr_[h] - 1e-6f;
    const float* up = g_u + (size_t)(b * TT + ck * CKL) * HH + h;
    float L = 0.f;
    float invp = INVDEC;
    float amin = 3.4e38f;
#pragma unroll
    for (int i = 0; i < CKL; i++) {
        L = fmaf(L, DECAYF, up[(size_t)i * HH] + bia);
        float cand = (thr - L) * invp;
        amin = fminf(amin, cand);
        invp *= INVDEC;
    }
    g_carry[(size_t)bc * HH + h] = L;
    g_amin [(size_t)bc * HH + h] = amin;
}

// ---------------- K2b: chain carries, flag firing neurons, zero counters -----
// 2 blocks x 512 threads; each lane owns 4 consecutive h of one batch.
__global__ __launch_bounds__(512) void scan_chain_kernel()
{
    int l  = blockIdx.x * 512 + threadIdx.x;   // 0..1023
    int b  = l >> 8;                           // 0..3
    int hq = (l & 255) * 4;

    // zero counters (2048 ints over 1024 lanes)
    g_cnt[l] = 0;
    g_cnt[l + 1024] = 0;

    // hoisted, independent loads: 16 chunks x (carry, amin) as float4
    float4 cr[NCK], am[NCK];
#pragma unroll
    for (int ck = 0; ck < NCK; ck++) {
        size_t idx = (size_t)(b * NCK + ck) * HH + hq;
        cr[ck] = *(const float4*)&g_carry[idx];
        am[ck] = *(const float4*)&g_amin[idx];
    }

    float4 m = make_float4(0.f, 0.f, 0.f, 0.f);
    int4 fire = make_int4(0, 0, 0, 0);
#pragma unroll
    for (int ck = 0; ck < NCK; ck++) {
        fire.x |= (m.x >= am[ck].x);
        fire.y |= (m.y >= am[ck].y);
        fire.z |= (m.z >= am[ck].z);
        fire.w |= (m.w >= am[ck].w);
        m.x = fmaf(m.x, DEC32F, cr[ck].x);
        m.y = fmaf(m.y, DEC32F, cr[ck].y);
        m.z = fmaf(m.z, DEC32F, cr[ck].z);
        m.w = fmaf(m.w, DEC32F, cr[ck].w);
    }
    *(int4*)&g_flag[b * HH + hq] = fire;
}

// ---------------- K2d: exact sequential repair for flagged neurons -----------
__global__ __launch_bounds__(512) void repair_kernel(
    const float* __restrict__ thr_, const float* __restrict__ b1)
{
    int b = blockIdx.x;
    int h = blockIdx.y * 512 + threadIdx.x;
    if (!g_flag[b * HH + h]) return;
    float thr = thr_[h];
    float bia = b1[h];
    float m = 0.f;
    for (int t = 0; t < TT; t++) {
        m = fmaf(m, DECAYF, g_u[(size_t)(b * TT + t) * HH + h] + bia);
        if (m >= thr) {
            int row = b * TT + t;
            int pos = atomicAdd(&g_cnt[row], 1);
            g_list[(size_t)row * HH + pos] = h;
            m = 0.f;
        }
    }
}

// ---------------- K3a: logits broadcast (side stream) ------------------------
#define BROWS 128   // rows per block -> 512 blocks total, fully co-resident
__global__ __launch_bounds__(256) void fc2_broadcast_kernel(
    const float* __restrict__ b2, float* __restrict__ out, long long out_size)
{
    int q = blockIdx.x * 256 + threadIdx.x;     // v-quad, 0..8191
    if (q < VV / 4) {
        float4 val = *(const float4*)(b2 + q * 4);
        int r0 = blockIdx.y * BROWS;
        float* p = out + (size_t)r0 * VV + q * 4;
#pragma unroll 8
        for (int i = 0; i < BROWS; i++) {
            __stcs((float4*)p, val);
            p += VV;
        }
    }
    // tail scalars (avg_spikes, mem_out) -> 0
    if (blockIdx.y == 0 && q == 0)
        for (long long t = NLOGITS; t < out_size; t++) out[t] = 0.f;
}

// ---------------- K3b: sparse spike corrections (post-scan + join) -----------
__global__ __launch_bounds__(256) void fc2_corr_kernel(
    const float* __restrict__ W2, float* __restrict__ out)
{
    int row = blockIdx.x;
    int k = g_cnt[row];
    if (k == 0) return;
    for (int v = threadIdx.x * 4; v < VV; v += 256 * 4) {
        float4 acc = make_float4(0.f, 0.f, 0.f, 0.f);
        for (int s = 0; s < k; s++) {
            int h = g_list[(size_t)row * HH + s];
            const float* w = W2 + (size_t)v * HH + h;
            acc.x += w[0];
            acc.y += w[HH];
            acc.z += w[2 * HH];
            acc.w += w[3 * HH];
        }
        float* p = out + (size_t)row * VV + v;
        float4 o = *(float4*)p;
        o.x += acc.x; o.y += acc.y; o.z += acc.z; o.w += acc.w;
        *(float4*)p = o;
    }
}

// ---------------- launcher: fork-join capture --------------------------------
extern "C" void kernel_launch(void* const* d_in, const int* in_sizes, int n_in,
                              void* d_out, int out_size)
{
    const int*   ids = (const int*)  d_in[0];
    const float* emb = (const float*)d_in[1];
    const float* W1  = (const float*)d_in[2];
    const float* b1  = (const float*)d_in[3];
    const float* W2  = (const float*)d_in[4];
    const float* b2  = (const float*)d_in[5];
    const float* thr = (const float*)d_in[6];
    float* out = (float*)d_out;

    static cudaStream_t s2 = nullptr;
    static cudaEvent_t evFork = nullptr, evJoin = nullptr;
    if (s2 == nullptr) {
        cudaStreamCreateWithFlags(&s2, cudaStreamNonBlocking);
        cudaEventCreateWithFlags(&evFork, cudaEventDisableTiming);
        cudaEventCreateWithFlags(&evJoin, cudaEventDisableTiming);
    }

    // Fork: b2 broadcast runs concurrently with the whole main path.
    cudaEventRecord(evFork, 0);
    cudaStreamWaitEvent(s2, evFork, 0);
    {
        dim3 gb(32, MM / BROWS);   // (32, 16) = 512 blocks
        fc2_broadcast_kernel<<<gb, 256, 0, s2>>>(b2, out, (long long)out_size);
    }
    cudaEventRecord(evJoin, s2);

    // Main path
    dim3 g1(HH / GBN, MM / GBM);                   // (8, 16)
    fc1_kernel<<<g1, 256>>>(ids, emb, W1);

    dim3 gs(BB * NCK, 2);                          // (64, 2) x 512
    scan_carry_kernel<<<gs, 512>>>(b1, thr);
    scan_chain_kernel<<<2, 512>>>();
    repair_kernel<<<dim3(BB, 2), 512>>>(thr, b1);

    // Join: corrections after broadcast + scan both complete.
    cudaStreamWaitEvent(0, evJoin, 0);
    fc2_corr_kernel<<<MM, 256>>>(W2, out);
}

// round 8
// speedup vs baseline: 1.3347x; 1.0512x over previous
#include <cuda_runtime.h>
#include <cuda_bf16.h>
#include <mma.h>
#include <cstdint>

using namespace nvcuda;

// Problem dims
#define BB 4
#define TT 512
#define DD 512
#define HH 1024
#define VV 32000
#define MM (BB*TT)                    // 2048 rows
#define NLOGITS ((long long)MM * VV)  // 65,536,000

#define DECAYF 0.60653065971263342f    // exp(-1/2)
#define INVDEC 1.64872127070012819f    // exp(+1/2)
#define DEC32F 1.1253517471925912e-07f // decay^32 = exp(-16)
#define NCK 16                         // time chunks
#define CKL 32                         // chunk length (NCK*CKL = TT)

// ---------------- scratch ----------------------------------------------------
__device__ float g_u[MM * HH];           // fc1 output (pre-bias), 8 MB (repair only)
__device__ int   g_cnt[MM];              // spikes per (b,t) row
__device__ int   g_list[MM * HH];        // spike h-indices per row
__device__ float g_carry[BB * NCK * HH]; // chunk carries
__device__ float g_amin[BB * NCK * HH];  // min chunk-start membrane that fires

// ---------------- K1: bf16 wmma GEMM + fused carry/amin epilogue -------------
#define GBM 128
#define GBN 128
#define GKC 32
#define KPAD 40    // 80B row pitch for bf16 stage tiles
#define CPITCH 132 // fp32 C-tile pitch (aliased over stage tiles)

// dynamic smem layout: [As 10240][Bs 10240][sids 512] aliased by [Cs 67584]
#define SMEM_FC1 (GBM * CPITCH * 4)

__global__ __launch_bounds__(256) void fc1_kernel(
    const int* __restrict__ ids, const float* __restrict__ emb,
    const float* __restrict__ W1, const float* __restrict__ b1,
    const float* __restrict__ thr_)
{
    extern __shared__ __align__(16) char smem_raw[];
    __nv_bfloat16 (*As)[KPAD] = (__nv_bfloat16(*)[KPAD])(smem_raw);
    __nv_bfloat16 (*Bs)[KPAD] = (__nv_bfloat16(*)[KPAD])(smem_raw + 10240);
    int*   sids = (int*)(smem_raw + 20480);
    float* Cs   = (float*)(smem_raw);            // aliased after mainloop

    const int bn  = blockIdx.x * GBN;
    const int bm  = blockIdx.y * GBM;
    const int tid = threadIdx.x;
    const int wid = tid >> 5;
    const int wm  = wid & 1;
    const int wn  = wid >> 1;

    // zero spike counters for this m-tile (ordered before chain_repair kernel)
    if (blockIdx.x == 0 && tid < GBM) g_cnt[bm + tid] = 0;

    if (tid < GBM) sids[tid] = ids[bm + tid];
    __syncthreads();

    wmma::fragment<wmma::accumulator, 16, 16, 16, float> c[4][2];
#pragma unroll
    for (int i = 0; i < 4; i++)
#pragma unroll
        for (int j = 0; j < 2; j++) wmma::fill_fragment(c[i][j], 0.f);

    for (int k0 = 0; k0 < DD; k0 += GKC) {
#pragma unroll
        for (int it = 0; it < 4; it++) {
            int idx = tid + it * 256;         // 0..1023
            int row = idx >> 3;               // 0..127
            int kq  = (idx & 7) * 4;          // 0,4,...,28
            {
                float4 v = *(const float4*)(emb + (size_t)sids[row] * DD + k0 + kq);
                __nv_bfloat162* d = (__nv_bfloat162*)&As[row][kq];
                d[0] = __float22bfloat162_rn(make_float2(v.x, v.y));
                d[1] = __float22bfloat162_rn(make_float2(v.z, v.w));
            }
            {
                float4 v = *(const float4*)(W1 + (size_t)(bn + row) * DD + k0 + kq);
                __nv_bfloat162* d = (__nv_bfloat162*)&Bs[row][kq];
                d[0] = __float22bfloat162_rn(make_float2(v.x, v.y));
                d[1] = __float22bfloat162_rn(make_float2(v.z, v.w));
            }
        }
        __syncthreads();

#pragma unroll
        for (int kk = 0; kk < GKC; kk += 16) {
            wmma::fragment<wmma::matrix_a, 16, 16, 16, __nv_bfloat16, wmma::row_major> a[4];
            wmma::fragment<wmma::matrix_b, 16, 16, 16, __nv_bfloat16, wmma::col_major> b[2];
#pragma unroll
            for (int i = 0; i < 4; i++)
                wmma::load_matrix_sync(a[i], &As[wm * 64 + i * 16][kk], KPAD);
#pragma unroll
            for (int j = 0; j < 2; j++)
                wmma::load_matrix_sync(b[j], &Bs[wn * 32 + j * 16][kk], KPAD);
#pragma unroll
            for (int i = 0; i < 4; i++)
#pragma unroll
                for (int j = 0; j < 2; j++)
                    wmma::mma_sync(c[i][j], a[i], b[j], c[i][j]);
        }
        __syncthreads();   // also protects the Cs alias below
    }

    // ---- epilogue: frags -> Cs (smem) ----
#pragma unroll
    for (int i = 0; i < 4; i++)
#pragma unroll
        for (int j = 0; j < 2; j++)
            wmma::store_matrix_sync(&Cs[(wm * 64 + i * 16) * CPITCH + wn * 32 + j * 16],
                                    c[i][j], CPITCH, wmma::mem_row_major);
    __syncthreads();

    // ---- write g_u tile (repair path needs it) ----
#pragma unroll
    for (int it = 0; it < 16; it++) {
        int idx  = tid + it * 256;            // 0..4095
        int row  = idx >> 5;                  // 0..127
        int col4 = (idx & 31) * 4;
        float4 v = *(const float4*)&Cs[row * CPITCH + col4];
        *(float4*)(g_u + (size_t)(bm + row) * HH + bn + col4) = v;
    }

    // ---- fused chunk carries + amin ----
    // block's t-range: 128 consecutive t of one batch (bm -> b, t0)
    const int b_  = bm >> 9;
    const int t0  = bm & 511;
#pragma unroll
    for (int rep = 0; rep < 2; rep++) {
        int task = tid + rep * 256;           // 0..511
        int ck   = task >> 7;                 // 0..3 local chunk
        int hcol = task & 127;
        int h    = bn + hcol;
        float bia = b1[h];
        float thr = thr_[h] - 1e-6f;
        float L = 0.f, invp = INVDEC, amin = 3.4e38f;
        const float* cp = &Cs[(ck * CKL) * CPITCH + hcol];
#pragma unroll
        for (int i = 0; i < CKL; i++) {
            L = fmaf(L, DECAYF, cp[i * CPITCH] + bia);
            float cand = (thr - L) * invp;
            amin = fminf(amin, cand);
            invp *= INVDEC;
        }
        size_t idx = (size_t)(b_ * NCK + (t0 >> 5) + ck) * HH + h;
        g_carry[idx] = L;
        g_amin [idx] = amin;
    }
}

// ---------------- K2: chain carries, flag+repair in one kernel ---------------
// 2 blocks x 512 threads; each lane owns 4 consecutive h of one batch.
__device__ __noinline__ void repair_one(int b, int h, float thr, float bia)
{
    float m = 0.f;
    for (int t = 0; t < TT; t++) {
        m = fmaf(m, DECAYF, g_u[(size_t)(b * TT + t) * HH + h] + bia);
        if (m >= thr) {
            int row = b * TT + t;
            int pos = atomicAdd(&g_cnt[row], 1);
            g_list[(size_t)row * HH + pos] = h;
            m = 0.f;
        }
    }
}

__global__ __launch_bounds__(512) void chain_repair_kernel(
    const float* __restrict__ thr_, const float* __restrict__ b1)
{
    int l  = blockIdx.x * 512 + threadIdx.x;   // 0..1023
    int b  = l >> 8;                           // 0..3
    int hq = (l & 255) * 4;

    float4 cr[NCK], am[NCK];
#pragma unroll
    for (int ck = 0; ck < NCK; ck++) {
        size_t idx = (size_t)(b * NCK + ck) * HH + hq;
        cr[ck] = *(const float4*)&g_carry[idx];
        am[ck] = *(const float4*)&g_amin[idx];
    }

    float4 m = make_float4(0.f, 0.f, 0.f, 0.f);
    int4 fire = make_int4(0, 0, 0, 0);
#pragma unroll
    for (int ck = 0; ck < NCK; ck++) {
        fire.x |= (m.x >= am[ck].x);
        fire.y |= (m.y >= am[ck].y);
        fire.z |= (m.z >= am[ck].z);
        fire.w |= (m.w >= am[ck].w);
        m.x = fmaf(m.x, DEC32F, cr[ck].x);
        m.y = fmaf(m.y, DEC32F, cr[ck].y);
        m.z = fmaf(m.z, DEC32F, cr[ck].z);
        m.w = fmaf(m.w, DEC32F, cr[ck].w);
    }

    if (fire.x) repair_one(b, hq + 0, thr_[hq + 0], b1[hq + 0]);
    if (fire.y) repair_one(b, hq + 1, thr_[hq + 1], b1[hq + 1]);
    if (fire.z) repair_one(b, hq + 2, thr_[hq + 2], b1[hq + 2]);
    if (fire.w) repair_one(b, hq + 3, thr_[hq + 3], b1[hq + 3]);
}

// ---------------- K3a: logits broadcast (side stream) ------------------------
#define BROWS 128   // rows per block -> 512 blocks, fully co-resident
__global__ __launch_bounds__(256) void fc2_broadcast_kernel(
    const float* __restrict__ b2, float* __restrict__ out, long long out_size)
{
    int q = blockIdx.x * 256 + threadIdx.x;     // v-quad, 0..8191
    if (q < VV / 4) {
        float4 val = *(const float4*)(b2 + q * 4);
        int r0 = blockIdx.y * BROWS;
        float* p = out + (size_t)r0 * VV + q * 4;
#pragma unroll 8
        for (int i = 0; i < BROWS; i++) {
            __stcs((float4*)p, val);
            p += VV;
        }
    }
    // tail scalars (avg_spikes, mem_out) -> 0
    if (blockIdx.y == 0 && q == 0)
        for (long long t = NLOGITS; t < out_size; t++) out[t] = 0.f;
}

// ---------------- K3b: sparse spike corrections (post-scan + join) -----------
__global__ __launch_bounds__(256) void fc2_corr_kernel(
    const float* __restrict__ W2, float* __restrict__ out)
{
    int row = blockIdx.x;
    int k = g_cnt[row];
    if (k == 0) return;
    for (int v = threadIdx.x * 4; v < VV; v += 256 * 4) {
        float4 acc = make_float4(0.f, 0.f, 0.f, 0.f);
        for (int s = 0; s < k; s++) {
            int h = g_list[(size_t)row * HH + s];
            const float* w = W2 + (size_t)v * HH + h;
            acc.x += w[0];
            acc.y += w[HH];
            acc.z += w[2 * HH];
            acc.w += w[3 * HH];
        }
        float* p = out + (size_t)row * VV + v;
        float4 o = *(float4*)p;
        o.x += acc.x; o.y += acc.y; o.z += acc.z; o.w += acc.w;
        *(float4*)p = o;
    }
}

// ---------------- launcher: fork-join capture --------------------------------
extern "C" void kernel_launch(void* const* d_in, const int* in_sizes, int n_in,
                              void* d_out, int out_size)
{
    const int*   ids = (const int*)  d_in[0];
    const float* emb = (const float*)d_in[1];
    const float* W1  = (const float*)d_in[2];
    const float* b1  = (const float*)d_in[3];
    const float* W2  = (const float*)d_in[4];
    const float* b2  = (const float*)d_in[5];
    const float* thr = (const float*)d_in[6];
    float* out = (float*)d_out;

    static cudaStream_t s2 = nullptr;
    static cudaEvent_t evFork = nullptr, evJoin = nullptr;
    if (s2 == nullptr) {
        cudaStreamCreateWithFlags(&s2, cudaStreamNonBlocking);
        cudaEventCreateWithFlags(&evFork, cudaEventDisableTiming);
        cudaEventCreateWithFlags(&evJoin, cudaEventDisableTiming);
        cudaFuncSetAttribute(fc1_kernel,
                             cudaFuncAttributeMaxDynamicSharedMemorySize, SMEM_FC1);
    }

    // Fork: b2 broadcast runs concurrently with the whole main path.
    cudaEventRecord(evFork, 0);
    cudaStreamWaitEvent(s2, evFork, 0);
    {
        dim3 gb(32, MM / BROWS);   // (32, 16) = 512 blocks
        fc2_broadcast_kernel<<<gb, 256, 0, s2>>>(b2, out, (long long)out_size);
    }
    cudaEventRecord(evJoin, s2);

    // Main path: fused GEMM+carry -> chain+repair
    dim3 g1(HH / GBN, MM / GBM);                   // (8, 16)
    fc1_kernel<<<g1, 256, SMEM_FC1>>>(ids, emb, W1, b1, thr);
    chain_repair_kernel<<<2, 512>>>(thr, b1);

    // Join: corrections after broadcast + scan both complete.
    cudaStreamWaitEvent(0, evJoin, 0);
    fc2_corr_kernel<<<MM, 256>>>(W2, out);
}

// round 9
// speedup vs baseline: 1.4218x; 1.0652x over previous
#include <cuda_runtime.h>
#include <cuda_bf16.h>
#include <mma.h>
#include <cstdint>

using namespace nvcuda;

// Problem dims
#define BB 4
#define TT 512
#define DD 512
#define HH 1024
#define VV 32000
#define MM (BB*TT)                    // 2048 rows
#define NLOGITS ((long long)MM * VV)  // 65,536,000

#define DECAYF 0.60653065971263342f    // exp(-1/2)
#define INVDEC 1.64872127070012819f    // exp(+1/2)
#define DEC32F 1.1253517471925912e-07f // decay^32 = exp(-16)
#define NCK 16                         // time chunks
#define CKL 32                         // chunk length (NCK*CKL = TT)

// ---------------- scratch ----------------------------------------------------
__device__ int   g_cnt[MM];              // spikes per (b,t) row
__device__ int   g_list[MM * HH];        // spike h-indices per row
__device__ float g_carry[BB * NCK * HH]; // chunk carries
__device__ float g_amin[BB * NCK * HH];  // min chunk-start membrane that fires

// ---------------- K1: bf16 wmma GEMM + fused carry/amin epilogue -------------
#define GBM 128
#define GBN 128
#define GKC 32
#define KPAD 40    // 80B row pitch for bf16 stage tiles
#define CPITCH 132 // fp32 C-tile pitch (aliased over stage tiles)
#define SMEM_FC1 (GBM * CPITCH * 4)

__global__ __launch_bounds__(256) void fc1_kernel(
    const int* __restrict__ ids, const float* __restrict__ emb,
    const float* __restrict__ W1, const float* __restrict__ b1,
    const float* __restrict__ thr_)
{
    extern __shared__ __align__(16) char smem_raw[];
    __nv_bfloat16 (*As)[KPAD] = (__nv_bfloat16(*)[KPAD])(smem_raw);
    __nv_bfloat16 (*Bs)[KPAD] = (__nv_bfloat16(*)[KPAD])(smem_raw + 10240);
    int*   sids = (int*)(smem_raw + 20480);
    float* Cs   = (float*)(smem_raw);            // aliased after mainloop

    const int bn  = blockIdx.x * GBN;
    const int bm  = blockIdx.y * GBM;
    const int tid = threadIdx.x;
    const int wid = tid >> 5;
    const int wm  = wid & 1;
    const int wn  = wid >> 1;

    // zero spike counters for this m-tile (ordered before chain_repair kernel)
    if (blockIdx.x == 0 && tid < GBM) g_cnt[bm + tid] = 0;

    if (tid < GBM) sids[tid] = ids[bm + tid];
    __syncthreads();

    wmma::fragment<wmma::accumulator, 16, 16, 16, float> c[4][2];
#pragma unroll
    for (int i = 0; i < 4; i++)
#pragma unroll
        for (int j = 0; j < 2; j++) wmma::fill_fragment(c[i][j], 0.f);

    for (int k0 = 0; k0 < DD; k0 += GKC) {
#pragma unroll
        for (int it = 0; it < 4; it++) {
            int idx = tid + it * 256;         // 0..1023
            int row = idx >> 3;               // 0..127
            int kq  = (idx & 7) * 4;          // 0,4,...,28
            {
                float4 v = *(const float4*)(emb + (size_t)sids[row] * DD + k0 + kq);
                __nv_bfloat162* d = (__nv_bfloat162*)&As[row][kq];
                d[0] = __float22bfloat162_rn(make_float2(v.x, v.y));
                d[1] = __float22bfloat162_rn(make_float2(v.z, v.w));
            }
            {
                float4 v = *(const float4*)(W1 + (size_t)(bn + row) * DD + k0 + kq);
                __nv_bfloat162* d = (__nv_bfloat162*)&Bs[row][kq];
                d[0] = __float22bfloat162_rn(make_float2(v.x, v.y));
                d[1] = __float22bfloat162_rn(make_float2(v.z, v.w));
            }
        }
        __syncthreads();

#pragma unroll
        for (int kk = 0; kk < GKC; kk += 16) {
            wmma::fragment<wmma::matrix_a, 16, 16, 16, __nv_bfloat16, wmma::row_major> a[4];
            wmma::fragment<wmma::matrix_b, 16, 16, 16, __nv_bfloat16, wmma::col_major> b[2];
#pragma unroll
            for (int i = 0; i < 4; i++)
                wmma::load_matrix_sync(a[i], &As[wm * 64 + i * 16][kk], KPAD);
#pragma unroll
            for (int j = 0; j < 2; j++)
                wmma::load_matrix_sync(b[j], &Bs[wn * 32 + j * 16][kk], KPAD);
#pragma unroll
            for (int i = 0; i < 4; i++)
#pragma unroll
                for (int j = 0; j < 2; j++)
                    wmma::mma_sync(c[i][j], a[i], b[j], c[i][j]);
        }
        __syncthreads();   // also protects the Cs alias below
    }

    // ---- epilogue: frags -> Cs (smem) ----
#pragma unroll
    for (int i = 0; i < 4; i++)
#pragma unroll
        for (int j = 0; j < 2; j++)
            wmma::store_matrix_sync(&Cs[(wm * 64 + i * 16) * CPITCH + wn * 32 + j * 16],
                                    c[i][j], CPITCH, wmma::mem_row_major);
    __syncthreads();

    // ---- fused chunk carries + amin (no g_u write: repair recomputes) ----
    const int b_  = bm >> 9;
    const int t0  = bm & 511;
#pragma unroll
    for (int rep = 0; rep < 2; rep++) {
        int task = tid + rep * 256;           // 0..511
        int ck   = task >> 7;                 // 0..3 local chunk
        int hcol = task & 127;
        int h    = bn + hcol;
        float bia = b1[h];
        float thr = thr_[h] - 1e-6f;
        float L = 0.f, invp = INVDEC, amin = 3.4e38f;
        const float* cp = &Cs[(ck * CKL) * CPITCH + hcol];
#pragma unroll
        for (int i = 0; i < CKL; i++) {
            L = fmaf(L, DECAYF, cp[i * CPITCH] + bia);
            float cand = (thr - L) * invp;
            amin = fminf(amin, cand);
            invp *= INVDEC;
        }
        size_t idx = (size_t)(b_ * NCK + (t0 >> 5) + ck) * HH + h;
        g_carry[idx] = L;
        g_amin [idx] = amin;
    }
}

// ---------------- K2: chain carries, flag + exact repair ---------------------
// Repair recomputes u_t[h] from emb/W1 with bf16-rounded inputs (fp32 accum):
// same precision envelope as the wmma path that produced the flags.
__device__ __noinline__ void repair_one(
    int b, int h, float thr, float bia,
    const int* __restrict__ ids, const float* __restrict__ emb,
    const float* __restrict__ W1)
{
    float m = 0.f;
    for (int t = 0; t < TT; t++) {
        const float* er = emb + (size_t)ids[b * TT + t] * DD;
        const float* wr = W1 + (size_t)h * DD;
        float u = 0.f;
        for (int d = 0; d < DD; d++) {
            float a = __bfloat162float(__float2bfloat16_rn(er[d]));
            float w = __bfloat162float(__float2bfloat16_rn(wr[d]));
            u = fmaf(a, w, u);
        }
        m = fmaf(m, DECAYF, u + bia);
        if (m >= thr) {
            int row = b * TT + t;
            int pos = atomicAdd(&g_cnt[row], 1);
            g_list[(size_t)row * HH + pos] = h;
            m = 0.f;
        }
    }
}

__global__ __launch_bounds__(512) void chain_repair_kernel(
    const float* __restrict__ thr_, const float* __restrict__ b1,
    const int* __restrict__ ids, const float* __restrict__ emb,
    const float* __restrict__ W1)
{
    int l  = blockIdx.x * 512 + threadIdx.x;   // 0..1023
    int b  = l >> 8;                           // 0..3
    int hq = (l & 255) * 4;

    float4 cr[NCK], am[NCK];
#pragma unroll
    for (int ck = 0; ck < NCK; ck++) {
        size_t idx = (size_t)(b * NCK + ck) * HH + hq;
        cr[ck] = *(const float4*)&g_carry[idx];
        am[ck] = *(const float4*)&g_amin[idx];
    }

    float4 m = make_float4(0.f, 0.f, 0.f, 0.f);
    int4 fire = make_int4(0, 0, 0, 0);
#pragma unroll
    for (int ck = 0; ck < NCK; ck++) {
        fire.x |= (m.x >= am[ck].x);
        fire.y |= (m.y >= am[ck].y);
        fire.z |= (m.z >= am[ck].z);
        fire.w |= (m.w >= am[ck].w);
        m.x = fmaf(m.x, DEC32F, cr[ck].x);
        m.y = fmaf(m.y, DEC32F, cr[ck].y);
        m.z = fmaf(m.z, DEC32F, cr[ck].z);
        m.w = fmaf(m.w, DEC32F, cr[ck].w);
    }

    if (fire.x) repair_one(b, hq + 0, thr_[hq + 0], b1[hq + 0], ids, emb, W1);
    if (fire.y) repair_one(b, hq + 1, thr_[hq + 1], b1[hq + 1], ids, emb, W1);
    if (fire.z) repair_one(b, hq + 2, thr_[hq + 2], b1[hq + 2], ids, emb, W1);
    if (fire.w) repair_one(b, hq + 3, thr_[hq + 3], b1[hq + 3], ids, emb, W1);
}

// ---------------- K3a: logits broadcast (side stream) ------------------------
#define BROWS 128   // rows per block -> 512 blocks, fully co-resident
__global__ __launch_bounds__(256) void fc2_broadcast_kernel(
    const float* __restrict__ b2, float* __restrict__ out, long long out_size)
{
    int q = blockIdx.x * 256 + threadIdx.x;     // v-quad, 0..8191
    if (q < VV / 4) {
        float4 val = *(const float4*)(b2 + q * 4);
        int r0 = blockIdx.y * BROWS;
        float* p = out + (size_t)r0 * VV + q * 4;
#pragma unroll 8
        for (int i = 0; i < BROWS; i++) {
            __stcs((float4*)p, val);
            p += VV;
        }
    }
    // tail scalars (avg_spikes, mem_out) -> 0
    if (blockIdx.y == 0 && q == 0)
        for (long long t = NLOGITS; t < out_size; t++) out[t] = 0.f;
}

// ---------------- K3b: sparse spike corrections (tiny worklist) --------------
// 16 blocks x 256 threads; block i owns rows [i*128, (i+1)*128).
__global__ __launch_bounds__(256) void fc2_corr_kernel(
    const float* __restrict__ W2, float* __restrict__ out)
{
    __shared__ int rows[128];
    __shared__ int nrows;
    const int base = blockIdx.x * 128;
    if (threadIdx.x == 0) nrows = 0;
    __syncthreads();
    if (threadIdx.x < 128) {
        if (g_cnt[base + threadIdx.x] != 0) {
            int p = atomicAdd(&nrows, 1);
            rows[p] = base + threadIdx.x;
        }
    }
    __syncthreads();
    for (int r = 0; r < nrows; r++) {
        int row = rows[r];
        int k = g_cnt[row];
        for (int v = threadIdx.x * 4; v < VV; v += 256 * 4) {
            float4 acc = make_float4(0.f, 0.f, 0.f, 0.f);
            for (int s = 0; s < k; s++) {
                int h = g_list[(size_t)row * HH + s];
                const float* w = W2 + (size_t)v * HH + h;
                acc.x += w[0];
                acc.y += w[HH];
                acc.z += w[2 * HH];
                acc.w += w[3 * HH];
            }
            float* p = out + (size_t)row * VV + v;
            float4 o = *(float4*)p;
            o.x += acc.x; o.y += acc.y; o.z += acc.z; o.w += acc.w;
            *(float4*)p = o;
        }
    }
}

// ---------------- launcher: fork-join capture --------------------------------
extern "C" void kernel_launch(void* const* d_in, const int* in_sizes, int n_in,
                              void* d_out, int out_size)
{
    const int*   ids = (const int*)  d_in[0];
    const float* emb = (const float*)d_in[1];
    const float* W1  = (const float*)d_in[2];
    const float* b1  = (const float*)d_in[3];
    const float* W2  = (const float*)d_in[4];
    const float* b2  = (const float*)d_in[5];
    const float* thr = (const float*)d_in[6];
    float* out = (float*)d_out;

    static cudaStream_t s2 = nullptr;
    static cudaEvent_t evFork = nullptr, evJoin = nullptr;
    if (s2 == nullptr) {
        cudaStreamCreateWithFlags(&s2, cudaStreamNonBlocking);
        cudaEventCreateWithFlags(&evFork, cudaEventDisableTiming);
        cudaEventCreateWithFlags(&evJoin, cudaEventDisableTiming);
        cudaFuncSetAttribute(fc1_kernel,
                             cudaFuncAttributeMaxDynamicSharedMemorySize, SMEM_FC1);
    }

    // Fork: b2 broadcast runs concurrently with the whole main path.
    cudaEventRecord(evFork, 0);
    cudaStreamWaitEvent(s2, evFork, 0);
    {
        dim3 gb(32, MM / BROWS);   // (32, 16) = 512 blocks
        fc2_broadcast_kernel<<<gb, 256, 0, s2>>>(b2, out, (long long)out_size);
    }
    cudaEventRecord(evJoin, s2);

    // Main path: fused GEMM+carry -> chain+repair
    dim3 g1(HH / GBN, MM / GBM);                   // (8, 16)
    fc1_kernel<<<g1, 256, SMEM_FC1>>>(ids, emb, W1, b1, thr);
    chain_repair_kernel<<<2, 512>>>(thr, b1, ids, emb, W1);

    // Join: corrections after broadcast + scan both complete.
    cudaStreamWaitEvent(0, evJoin, 0);
    fc2_corr_kernel<<<16, 256>>>(W2, out);
}